// round 1
// baseline (speedup 1.0000x reference)
#include <cuda_runtime.h>

#define BB 8
#define TT 512
#define DD 64
#define TILE 32
#define NT (TT / TILE)               // 16 tiles per dim
#define NPAIR (NT * (NT + 1) / 2)    // 136 upper-tri tile pairs

// Scratch for v = x @ W^T + b  (B*T*D floats = 512 KB). Static device global:
// allocation-free per harness rules.
__device__ float g_v[BB * TT * DD];

// ---------------------------------------------------------------------------
// Kernel 1: v[b,t,e] = sum_d x[b,t,d] * W[e,d] + bias[e]
// One thread per output element; W staged transposed in shared for
// conflict-free LDS (lanes index consecutive e).
// ---------------------------------------------------------------------------
__global__ __launch_bounds__(256)
void v_kernel(const float* __restrict__ x, const float* __restrict__ W,
              const float* __restrict__ bias) {
    __shared__ float sWT[DD * DD];   // sWT[d*64 + e] = W[e*64 + d]
    int tid = threadIdx.x;
    for (int k = tid; k < DD * DD; k += 256) {
        int d = k >> 6, e = k & 63;
        sWT[k] = W[e * DD + d];
    }
    __syncthreads();

    int idx = blockIdx.x * 256 + tid;        // [0, B*T*D)
    int e = idx & 63;
    const float* xrow = x + (idx >> 6) * DD; // row of x for this (b,t)
    float acc = bias[e];
#pragma unroll
    for (int d = 0; d < DD; d++)
        acc = fmaf(xrow[d], sWT[d * DD + e], acc);
    g_v[idx] = acc;
}

// ---------------------------------------------------------------------------
// Kernel 2: pairwise RBF softmax-weighted output, exploiting (i,j) symmetry.
// Block = (batch b, upper-tri tile pair (ti,tj)). 256 threads, each computes
// a 2x2 register sub-tile of pairs. Shared tiles stored transposed [d][row]
// (pad 34) so float2 loads over two rows are conflict-free.
// Emits out[b,i,j] = num_i/den and (off-diag) out[b,j,i] = num_j/den.
// ---------------------------------------------------------------------------
__global__ __launch_bounds__(256)
void rbf_kernel(const float* __restrict__ x, float* __restrict__ out) {
    __shared__ float xiT[DD][34];
    __shared__ float xjT[DD][34];
    __shared__ float viT[DD][34];
    __shared__ float vjT[DD][34];

    int b = blockIdx.y;
    int p = blockIdx.x;
    // decode upper-tri pair index -> (ti, tj), tj >= ti
    int ti = 0, rem = p;
    while (rem >= NT - ti) { rem -= NT - ti; ti++; }
    int tj = ti + rem;
    int i0 = ti * TILE, j0 = tj * TILE;

    int tid = threadIdx.x;
    const float* xb = x + b * TT * DD;
    const float* vb = g_v + b * TT * DD;

    // Stage tiles (32 rows x 64 d) transposed. Coalesced global reads.
#pragma unroll
    for (int k = 0; k < 8; k++) {
        int idx = tid + k * 256;     // [0, 2048)
        int r = idx >> 6, d = idx & 63;
        xiT[d][r] = xb[i0 * DD + idx];
        xjT[d][r] = xb[j0 * DD + idx];
        viT[d][r] = vb[i0 * DD + idx];
        vjT[d][r] = vb[j0 * DD + idx];
    }
    __syncthreads();

    int tx = tid & 15, ty = tid >> 4;
    int ii = 2 * ty;                 // local i rows: ii, ii+1
    int jj = 2 * tx;                 // local j rows: jj, jj+1

    float den00 = 0.f, den01 = 0.f, den10 = 0.f, den11 = 0.f;
    float ni00 = 0.f, ni01 = 0.f, ni10 = 0.f, ni11 = 0.f;
    float nj00 = 0.f, nj01 = 0.f, nj10 = 0.f, nj11 = 0.f;

#pragma unroll 4
    for (int d = 0; d < DD; d++) {
        float2 fi = *(const float2*)&xiT[d][ii];
        float2 fj = *(const float2*)&xjT[d][jj];
        float2 vi = *(const float2*)&viT[d][ii];
        float2 vj = *(const float2*)&vjT[d][jj];

        float d00 = fi.x - fj.x;
        float d01 = fi.x - fj.y;
        float d10 = fi.y - fj.x;
        float d11 = fi.y - fj.y;

        float e00 = __expf(-(d00 * d00));
        float e01 = __expf(-(d01 * d01));
        float e10 = __expf(-(d10 * d10));
        float e11 = __expf(-(d11 * d11));

        den00 += e00; den01 += e01; den10 += e10; den11 += e11;
        ni00 = fmaf(e00, vi.x, ni00);
        ni01 = fmaf(e01, vi.x, ni01);
        ni10 = fmaf(e10, vi.y, ni10);
        ni11 = fmaf(e11, vi.y, ni11);
        nj00 = fmaf(e00, vj.x, nj00);
        nj01 = fmaf(e01, vj.y, nj01);
        nj10 = fmaf(e10, vj.x, nj10);
        nj11 = fmaf(e11, vj.y, nj11);
    }

    float r00 = __fdividef(1.0f, den00);
    float r01 = __fdividef(1.0f, den01);
    float r10 = __fdividef(1.0f, den10);
    float r11 = __fdividef(1.0f, den11);

    int gi = i0 + ii;
    int gj = j0 + jj;
    float* ob = out + (size_t)b * TT * TT;

    // main writes: out[b, gi..gi+1, gj..gj+1] (coalesced across tx)
    ob[(size_t)gi * TT + gj]           = ni00 * r00;
    ob[(size_t)gi * TT + gj + 1]       = ni01 * r01;
    ob[(size_t)(gi + 1) * TT + gj]     = ni10 * r10;
    ob[(size_t)(gi + 1) * TT + gj + 1] = ni11 * r11;

    if (ti != tj) {
        // mirrored writes: out[b, j, i] = num_j / den
        ob[(size_t)gj * TT + gi]           = nj00 * r00;
        ob[(size_t)gj * TT + gi + 1]       = nj10 * r10;
        ob[(size_t)(gj + 1) * TT + gi]     = nj01 * r01;
        ob[(size_t)(gj + 1) * TT + gi + 1] = nj11 * r11;
    }
}

extern "C" void kernel_launch(void* const* d_in, const int* in_sizes, int n_in,
                              void* d_out, int out_size) {
    const float* x = (const float*)d_in[0];   // (8,512,64)
    const float* W = (const float*)d_in[1];   // (64,64)
    const float* bias = (const float*)d_in[2];// (64,)
    float* out = (float*)d_out;               // (8,512,512)

    v_kernel<<<(BB * TT * DD) / 256, 256>>>(x, W, bias);
    rbf_kernel<<<dim3(NPAIR, BB), 256>>>(x, out);
}

// round 2
// speedup vs baseline: 1.7285x; 1.7285x over previous
#include <cuda_runtime.h>

#define BB 8
#define TT 512
#define DD 64
#define TILE 64
#define NT (TT / TILE)               // 8 tiles per dim
#define NPAIR (NT * (NT + 1) / 2)    // 36 upper-tri tile pairs
#define PAD 65                        // row pad (floats) for conflict-free LDS/STS

// sqrt(log2(e)): pre-scaling x by this lets exp(-(dx)^2) = ex2(-(s*dx)^2)
#define SQRT_LOG2E 1.2011224087864498f

// Scratch for v = x @ W^T + b  (B*T*D floats = 512 KB).
__device__ float g_v[BB * TT * DD];

__device__ __forceinline__ float ex2f(float x) {
    float r;
    asm("ex2.approx.ftz.f32 %0, %1;" : "=f"(r) : "f"(x));
    return r;
}

// ---------------------------------------------------------------------------
// Kernel 1: v[b,t,e] = sum_d x[b,t,d] * W[e,d] + bias[e]
// 128 blocks, each handles 32 (b,t) rows. W staged transposed (pad-65) once
// per block: conflict-free STS (consecutive d) and LDS (consecutive e).
// ---------------------------------------------------------------------------
__global__ __launch_bounds__(256)
void v_kernel(const float* __restrict__ x, const float* __restrict__ W,
              const float* __restrict__ bias) {
    __shared__ float sWT[DD * PAD];      // sWT[d*PAD + e] = W[e*DD + d]
    __shared__ float sX[32 * DD];        // 32 rows of x, natural layout

    int tid = threadIdx.x;
    int row0 = blockIdx.x * 32;          // first (b,t) row for this block

    // stage W transposed: read coalesced (k = e*64 + d), write conflict-free
    for (int k = tid; k < DD * DD; k += 256) {
        int e = k >> 6, d = k & 63;
        sWT[d * PAD + e] = W[k];
    }
    // stage 32 x-rows coalesced
    for (int k = tid; k < 32 * DD; k += 256)
        sX[k] = x[row0 * DD + k];
    __syncthreads();

    int e = tid & 63;
    int rg = tid >> 6;                   // 0..3
    float be = bias[e];
#pragma unroll
    for (int k = 0; k < 8; k++) {
        int r = rg + 4 * k;              // local row 0..31
        float acc = be;
#pragma unroll
        for (int d = 0; d < DD; d++)
            acc = fmaf(sX[r * DD + d], sWT[d * PAD + e], acc);
        g_v[(row0 + r) * DD + e] = acc;
    }
}

// ---------------------------------------------------------------------------
// Kernel 2: pairwise RBF softmax-weighted output with (i,j) symmetry.
// Block = (b, upper-tri pair of 64x64 tiles). 256 threads, each owns a 4x4
// sub-tile. Shared tiles in natural [row][d] layout, rows padded to 65 floats
// so per-d scalar LDS across tx is conflict-free. x tiles pre-scaled by
// sqrt(log2 e) so exp costs one FMUL(-d,d) + one EX2.
// ---------------------------------------------------------------------------
__global__ __launch_bounds__(256)
void rbf_kernel(const float* __restrict__ x, float* __restrict__ out) {
    extern __shared__ float smem[];
    float* xi = smem;                          // TILE*PAD
    float* xj = xi + TILE * PAD;
    float* vi = xj + TILE * PAD;
    float* vj = vi + TILE * PAD;

    int b = blockIdx.y;
    int p = blockIdx.x;
    int ti = 0, rem = p;
    while (rem >= NT - ti) { rem -= NT - ti; ti++; }
    int tj = ti + rem;
    int i0 = ti * TILE, j0 = tj * TILE;

    int tid = threadIdx.x;
    const float* xb = x + b * TT * DD;
    const float* vb = g_v + b * TT * DD;

    // Stage tiles: coalesced global reads; STS conflict-free (consecutive d).
#pragma unroll
    for (int k = 0; k < 16; k++) {
        int idx = tid + k * 256;               // [0, 4096)
        int r = idx >> 6, d = idx & 63;
        int sa = r * PAD + d;
        xi[sa] = SQRT_LOG2E * xb[i0 * DD + idx];
        xj[sa] = SQRT_LOG2E * xb[j0 * DD + idx];
        vi[sa] = vb[i0 * DD + idx];
        vj[sa] = vb[j0 * DD + idx];
    }
    __syncthreads();

    int tx = tid & 15, ty = tid >> 4;
    int ii = 4 * ty;                            // local i rows ii..ii+3
    int jj = 4 * tx;                            // local j rows jj..jj+3

    float den[4][4], ni[4][4], nj[4][4];
#pragma unroll
    for (int r = 0; r < 4; r++)
#pragma unroll
        for (int c = 0; c < 4; c++) { den[r][c] = 0.f; ni[r][c] = 0.f; nj[r][c] = 0.f; }

#pragma unroll 2
    for (int d = 0; d < DD; d++) {
        float fi[4], fv[4], fj[4], jv[4];
#pragma unroll
        for (int r = 0; r < 4; r++) {
            fi[r] = xi[(ii + r) * PAD + d];     // broadcast across tx
            fv[r] = vi[(ii + r) * PAD + d];
        }
#pragma unroll
        for (int c = 0; c < 4; c++) {
            fj[c] = xj[(jj + c) * PAD + d];     // conflict-free across tx
            jv[c] = vj[(jj + c) * PAD + d];
        }
#pragma unroll
        for (int r = 0; r < 4; r++) {
#pragma unroll
            for (int c = 0; c < 4; c++) {
                float dd = fi[r] - fj[c];
                float e  = ex2f(-dd * dd);      // FMUL(neg) + MUFU.EX2
                den[r][c] += e;
                ni[r][c] = fmaf(e, fv[r], ni[r][c]);
                nj[r][c] = fmaf(e, jv[c], nj[r][c]);
            }
        }
    }

    int gi = i0 + ii;
    int gj = j0 + jj;
    float* ob = out + (size_t)b * TT * TT;

    float oi[4][4], oj[4][4];
#pragma unroll
    for (int r = 0; r < 4; r++)
#pragma unroll
        for (int c = 0; c < 4; c++) {
            float rc;
            asm("rcp.approx.ftz.f32 %0, %1;" : "=f"(rc) : "f"(den[r][c]));
            oi[r][c] = ni[r][c] * rc;
            oj[r][c] = nj[r][c] * rc;
        }

    // main writes: out[b, gi+r, gj..gj+3] — float4, coalesced across tx
#pragma unroll
    for (int r = 0; r < 4; r++) {
        float4 w = make_float4(oi[r][0], oi[r][1], oi[r][2], oi[r][3]);
        *(float4*)&ob[(size_t)(gi + r) * TT + gj] = w;
    }

    if (ti != tj) {
        // mirror writes: out[b, gj+c, gi..gi+3] = nj/den (transposed sub-tile)
#pragma unroll
        for (int c = 0; c < 4; c++) {
            float4 w = make_float4(oj[0][c], oj[1][c], oj[2][c], oj[3][c]);
            *(float4*)&ob[(size_t)(gj + c) * TT + gi] = w;
        }
    }
}

extern "C" void kernel_launch(void* const* d_in, const int* in_sizes, int n_in,
                              void* d_out, int out_size) {
    const float* x = (const float*)d_in[0];    // (8,512,64)
    const float* W = (const float*)d_in[1];    // (64,64)
    const float* bias = (const float*)d_in[2]; // (64,)
    float* out = (float*)d_out;                // (8,512,512)

    static bool attr_set = false;
    size_t smem_bytes = 4 * TILE * PAD * sizeof(float);   // 66560
    if (!attr_set) {
        cudaFuncSetAttribute(rbf_kernel,
                             cudaFuncAttributeMaxDynamicSharedMemorySize,
                             (int)smem_bytes);
        attr_set = true;
    }

    v_kernel<<<(BB * TT) / 32, 256>>>(x, W, bias);
    rbf_kernel<<<dim3(NPAIR, BB), 256, smem_bytes>>>(x, out);
}